// round 4
// baseline (speedup 1.0000x reference)
#include <cuda_runtime.h>
#include <math.h>

// ---------------------------------------------------------------------------
// Model1_11596411699487: 5x 4D conv (valid, stride 1) + ReLU, flatten,
// dense 1280->33 + ReLU, dense 33->2, softmax.
//
// Round 4: padded z-strides on intermediates so every row load is
// LDG.128/LDG.64 (L1-wavefront reduction), ZG z-split on conv2 for occupancy.
// ---------------------------------------------------------------------------

#define BATCH 256

// Padded z-strides: h1:16 (15), h2:12 (nat), h3:12 (9), h4:8 (6), h5:4 (nat).
__device__ float g_h1[BATCH * 3 * 15 * 15 * 15 * 16];  // 166 MB
__device__ float g_h2[BATCH * 3 * 12 * 12 * 12 * 12];  //  64 MB
__device__ float g_h3[BATCH * 4 * 9 * 9 * 9 * 12];     //  36 MB
__device__ float g_h4[BATCH * 5 * 6 * 6 * 6 * 8];      //   9 MB
__device__ float g_h5[BATCH * 5 * 4 * 4 * 4 * 4];      // 1.3 MB (exact, feeds head)

// Exact-length vectorized row load. ALIGN = compile-time guaranteed alignment
// (in floats) of p. Decomposes EXT into float4 / float2 / float chunks.
template <int EXT, int ALIGN>
__device__ __forceinline__ void load_row(float* __restrict__ r,
                                         const float* __restrict__ p)
{
    constexpr int N4 = (ALIGN >= 4) ? EXT / 4 : 0;
    constexpr int R4 = EXT - 4 * N4;
    constexpr int N2 = (ALIGN >= 2) ? R4 / 2 : 0;
    constexpr int N1 = R4 - 2 * N2;
#pragma unroll
    for (int j = 0; j < N4; j++) {
        float4 v = *(const float4*)(p + 4 * j);
        r[4 * j + 0] = v.x; r[4 * j + 1] = v.y;
        r[4 * j + 2] = v.z; r[4 * j + 3] = v.w;
    }
#pragma unroll
    for (int j = 0; j < N2; j++) {
        float2 v = *(const float2*)(p + 4 * N4 + 2 * j);
        r[4 * N4 + 2 * j + 0] = v.x;
        r[4 * N4 + 2 * j + 1] = v.y;
    }
#pragma unroll
    for (int j = 0; j < N1; j++)
        r[4 * N4 + 2 * N2 + j] = p[4 * N4 + 2 * N2 + j];
}

// ---------------------------------------------------------------------------
// Direct 4D conv + ReLU.
// Thread owns (cog, zg, b, w0, x0, y0): computes ZC z-outputs for CPG channels.
// Per (ci,kw,kx): batch-load all K ky-rows (vectorized), batch-load weights,
// then dense FFMA block.
//   PSin/PSout: padded z-strides of input/output tensors.
//   ALIGN: guaranteed alignment (floats) of every row base.
// ---------------------------------------------------------------------------
template <int Cin, int Cout, int Sin, int K, int COG, int ZG,
          int PSin, int PSout, int ALIGN>
__global__ void __launch_bounds__(128)
conv4d_relu_kernel(const float* __restrict__ in,
                   const float* __restrict__ wt,
                   const float* __restrict__ bias,
                   float* __restrict__ out)
{
    constexpr int Sout = Sin - K + 1;
    static_assert(Sout % ZG == 0, "z split must divide Sout");
    constexpr int ZC  = Sout / ZG;
    constexpr int EXT = ZC + K - 1;
    constexpr int CPG = (Cout + COG - 1) / COG;
    constexpr int WSZ = Cout * Cin * K * K * K * K;
    constexpr int NPOS = Sout * Sout * Sout;
    static_assert(PSin % ALIGN == 0, "stride alignment");
    static_assert(ZG == 1 || (ZC % ALIGN) == 0, "z0 alignment");

    __shared__ float sw[WSZ];
    __shared__ float sb[Cout];
    for (int i = threadIdx.x; i < WSZ; i += blockDim.x) sw[i] = wt[i];
    if (threadIdx.x < Cout) sb[threadIdx.x] = bias[threadIdx.x];
    __syncthreads();

    int tid = blockIdx.x * blockDim.x + threadIdx.x;
    if (tid >= BATCH * NPOS * COG * ZG) return;

    int y0 = tid % Sout;
    int t1 = tid / Sout;
    int x0 = t1 % Sout;
    int t2 = t1 / Sout;
    int w0 = t2 % Sout;
    int t3 = t2 / Sout;
    int b  = t3 % BATCH;
    int g  = t3 / BATCH;
    int cog = g % COG;
    int zg  = g / COG;
    int co0 = cog * CPG;
    int z0  = zg * ZC;

    float acc[CPG * ZC];
#pragma unroll
    for (int c = 0; c < CPG; c++) {
        float bv = (co0 + c < Cout) ? sb[co0 + c] : 0.0f;
#pragma unroll
        for (int z = 0; z < ZC; z++) acc[c * ZC + z] = bv;
    }

#pragma unroll 1
    for (int ci = 0; ci < Cin; ci++) {
#pragma unroll 1
        for (int kw = 0; kw < K; kw++) {
#pragma unroll 1
            for (int kx = 0; kx < K; kx++) {
                const float* base = in +
                    (size_t)((((b * Cin + ci) * Sin + (w0 + kw)) * Sin + (x0 + kx)) * Sin
                             + y0) * PSin + z0;
                float r[K][EXT];
#pragma unroll
                for (int ky = 0; ky < K; ky++)
                    load_row<EXT, ALIGN>(r[ky], base + ky * PSin);

#pragma unroll
                for (int ky = 0; ky < K; ky++) {
                    // batch weight loads for this (ci,kw,kx,ky)
                    float wv[CPG * K];
#pragma unroll
                    for (int c = 0; c < CPG; c++) {
                        int co = co0 + c;
                        if (co >= Cout) break;
#pragma unroll
                        for (int kz = 0; kz < K; kz++)
                            wv[c * K + kz] =
                                sw[((((co * Cin + ci) * K + kw) * K + kx) * K + ky) * K + kz];
                    }
#pragma unroll
                    for (int c = 0; c < CPG; c++) {
                        int co = co0 + c;
                        if (co >= Cout) break;
#pragma unroll
                        for (int kz = 0; kz < K; kz++) {
                            float w = wv[c * K + kz];
#pragma unroll
                            for (int z = 0; z < ZC; z++)
                                acc[c * ZC + z] += r[ky][z + kz] * w;
                        }
                    }
                }
            }
        }
    }

#pragma unroll
    for (int c = 0; c < CPG; c++) {
        int co = co0 + c;
        if (co >= Cout) break;
        float* op = out +
            (size_t)((((b * Cout + co) * Sout + w0) * Sout + x0) * Sout + y0) * PSout + z0;
#pragma unroll
        for (int z = 0; z < ZC; z++)
            op[z] = fmaxf(acc[c * ZC + z], 0.0f);
    }
}

// ---------------------------------------------------------------------------
// Head: per-sample block. dense 1280->33 (ReLU), dense 33->2, softmax.
// ---------------------------------------------------------------------------
__global__ void __launch_bounds__(64)
head_kernel(const float* __restrict__ h,
            const float* __restrict__ dw1, const float* __restrict__ db1,
            const float* __restrict__ dw2, const float* __restrict__ db2,
            float* __restrict__ out)
{
    int b = blockIdx.x;
    __shared__ float sh[1280];
    __shared__ float s1[33];

    for (int i = threadIdx.x; i < 1280; i += blockDim.x)
        sh[i] = h[b * 1280 + i];
    __syncthreads();

    int j = threadIdx.x;
    if (j < 33) {
        float s = db1[j];
        const float* wr = dw1 + j * 1280;
#pragma unroll 4
        for (int i = 0; i < 1280; i++) s += wr[i] * sh[i];
        s1[j] = fmaxf(s, 0.0f);
    }
    __syncthreads();

    if (threadIdx.x == 0) {
        float l0 = db2[0], l1 = db2[1];
        for (int jj = 0; jj < 33; jj++) {
            l0 += dw2[jj] * s1[jj];
            l1 += dw2[33 + jj] * s1[jj];
        }
        float m  = fmaxf(l0, l1);
        float e0 = expf(l0 - m);
        float e1 = expf(l1 - m);
        float inv = 1.0f / (e0 + e1);
        out[b * 2 + 0] = e0 * inv;
        out[b * 2 + 1] = e1 * inv;
    }
}

static inline int cdiv(int a, int b) { return (a + b - 1) / b; }

extern "C" void kernel_launch(void* const* d_in, const int* in_sizes, int n_in,
                              void* d_out, int out_size)
{
    const float* x   = (const float*)d_in[0];
    const float* w1  = (const float*)d_in[1];
    const float* b1  = (const float*)d_in[2];
    const float* w2  = (const float*)d_in[3];
    const float* b2  = (const float*)d_in[4];
    const float* w3  = (const float*)d_in[5];
    const float* b3  = (const float*)d_in[6];
    const float* w4  = (const float*)d_in[7];
    const float* b4  = (const float*)d_in[8];
    const float* w5  = (const float*)d_in[9];
    const float* b5  = (const float*)d_in[10];
    const float* dw1 = (const float*)d_in[11];
    const float* db1 = (const float*)d_in[12];
    const float* dw2 = (const float*)d_in[13];
    const float* db2 = (const float*)d_in[14];
    float* out = (float*)d_out;

    float *h1, *h2, *h3, *h4, *h5;
    cudaGetSymbolAddress((void**)&h1, g_h1);
    cudaGetSymbolAddress((void**)&h2, g_h2);
    cudaGetSymbolAddress((void**)&h3, g_h3);
    cudaGetSymbolAddress((void**)&h4, g_h4);
    cudaGetSymbolAddress((void**)&h5, g_h5);

    const int T = 128;

    // conv1: 1->3, 18->15, k=4. x stride 18 (even) -> float2. out h1 stride 16.
    conv4d_relu_kernel<1, 3, 18, 4, 1, 1, 18, 16, 2>
        <<<cdiv(BATCH * 15 * 15 * 15, T), T>>>(x, w1, b1, h1);
    // conv2: 3->3, 15->12, k=4. in h1 stride 16, z-split 2 (z0 in {0,6}) -> float2.
    conv4d_relu_kernel<3, 3, 15, 4, 1, 2, 16, 12, 2>
        <<<cdiv(BATCH * 12 * 12 * 12 * 2, T), T>>>(h1, w2, b2, h2);
    // conv3: 3->4, 12->9, k=4. in h2 stride 12 (16B aligned) -> float4. out h3 stride 12.
    conv4d_relu_kernel<3, 4, 12, 4, 1, 1, 12, 12, 4>
        <<<cdiv(BATCH * 9 * 9 * 9, T), T>>>(h2, w3, b3, h3);
    // conv4: 4->5, 9->6, k=4. in h3 stride 12 -> float4. co split x2. out h4 stride 8.
    conv4d_relu_kernel<4, 5, 9, 4, 2, 1, 12, 8, 4>
        <<<cdiv(BATCH * 6 * 6 * 6 * 2, T), T>>>(h3, w4, b4, h4);
    // conv5: 5->5, 6->4, k=3. in h4 stride 8 -> float4. co split x5. out h5 exact.
    conv4d_relu_kernel<5, 5, 6, 3, 5, 1, 8, 4, 4>
        <<<cdiv(BATCH * 4 * 4 * 4 * 5, T), T>>>(h4, w5, b5, h5);
    // head
    head_kernel<<<BATCH, 64>>>(h5, dw1, db1, dw2, db2, out);
}

// round 8
// speedup vs baseline: 1.6227x; 1.6227x over previous
#include <cuda_runtime.h>
#include <math.h>

// ---------------------------------------------------------------------------
// Model1_11596411699487: 5x 4D conv (valid, stride 1) + ReLU, flatten,
// dense 1280->33 + ReLU, dense 33->2, softmax.
//
// Round 5: conv1/conv2 exactly as round 3 (known good). conv3/4/5 keep the
// measured round-4 wins: float4 row loads + padded h3/h4 strides + batched
// weight LDS. No other deltas.
// ---------------------------------------------------------------------------

#define BATCH 256

__device__ float g_h1[BATCH * 3 * 15 * 15 * 15 * 15];  // natural stride 15
__device__ float g_h2[BATCH * 3 * 12 * 12 * 12 * 12];  // natural stride 12 (16B aligned)
__device__ float g_h3[BATCH * 4 * 9 * 9 * 9 * 12];     // z-stride padded 9->12
__device__ float g_h4[BATCH * 5 * 6 * 6 * 6 * 8];      // z-stride padded 6->8
__device__ float g_h5[BATCH * 5 * 4 * 4 * 4 * 4];      // exact (feeds head)

// Exact-length vectorized row load. ALIGN = compile-time guaranteed alignment
// (in floats) of p.
template <int EXT, int ALIGN>
__device__ __forceinline__ void load_row(float* __restrict__ r,
                                         const float* __restrict__ p)
{
    constexpr int N4 = (ALIGN >= 4) ? EXT / 4 : 0;
    constexpr int R4 = EXT - 4 * N4;
    constexpr int N2 = (ALIGN >= 2) ? R4 / 2 : 0;
    constexpr int N1 = R4 - 2 * N2;
#pragma unroll
    for (int j = 0; j < N4; j++) {
        float4 v = *(const float4*)(p + 4 * j);
        r[4 * j + 0] = v.x; r[4 * j + 1] = v.y;
        r[4 * j + 2] = v.z; r[4 * j + 3] = v.w;
    }
#pragma unroll
    for (int j = 0; j < N2; j++) {
        float2 v = *(const float2*)(p + 4 * N4 + 2 * j);
        r[4 * N4 + 2 * j + 0] = v.x;
        r[4 * N4 + 2 * j + 1] = v.y;
    }
#pragma unroll
    for (int j = 0; j < N1; j++)
        r[4 * N4 + 2 * N2 + j] = p[4 * N4 + 2 * N2 + j];
}

// ---------------------------------------------------------------------------
// Direct 4D conv + ReLU.
// Thread owns (cog, b, w0, x0, y0): all Sout z outputs for CPG channels.
// Per (ci,kw,kx): batch-load all K ky-rows, then dense FFMA block.
//   PSin/PSout: z-strides of input/output tensors (padded where noted).
//   ALIGN: guaranteed alignment (floats) of every row base.
//   WB: batch weight LDS into registers per ky (round-4 style) vs inline LDS
//       (round-3 style) — kept split so conv1/conv2 match round 3 exactly.
// ---------------------------------------------------------------------------
template <int Cin, int Cout, int Sin, int K, int COG,
          int PSin, int PSout, int ALIGN, int WB>
__global__ void __launch_bounds__(128)
conv4d_relu_kernel(const float* __restrict__ in,
                   const float* __restrict__ wt,
                   const float* __restrict__ bias,
                   float* __restrict__ out)
{
    constexpr int Sout = Sin - K + 1;
    constexpr int CPG  = (Cout + COG - 1) / COG;
    constexpr int WSZ  = Cout * Cin * K * K * K * K;
    constexpr int NPOS = Sout * Sout * Sout;

    __shared__ float sw[WSZ];
    __shared__ float sb[Cout];
    for (int i = threadIdx.x; i < WSZ; i += blockDim.x) sw[i] = wt[i];
    if (threadIdx.x < Cout) sb[threadIdx.x] = bias[threadIdx.x];
    __syncthreads();

    int tid = blockIdx.x * blockDim.x + threadIdx.x;
    if (tid >= BATCH * NPOS * COG) return;

    int y0 = tid % Sout;
    int t1 = tid / Sout;
    int x0 = t1 % Sout;
    int t2 = t1 / Sout;
    int w0 = t2 % Sout;
    int t3 = t2 / Sout;
    int b  = t3 % BATCH;
    int g  = t3 / BATCH;
    int co0 = g * CPG;

    float acc[CPG * Sout];
#pragma unroll
    for (int c = 0; c < CPG; c++) {
        float bv = (co0 + c < Cout) ? sb[co0 + c] : 0.0f;
#pragma unroll
        for (int z = 0; z < Sout; z++) acc[c * Sout + z] = bv;
    }

#pragma unroll 1
    for (int ci = 0; ci < Cin; ci++) {
#pragma unroll 1
        for (int kw = 0; kw < K; kw++) {
#pragma unroll 1
            for (int kx = 0; kx < K; kx++) {
                const float* base = in +
                    ((((b * Cin + ci) * Sin + (w0 + kw)) * Sin + (x0 + kx)) * Sin
                     + y0) * PSin;
                float r[K][Sin];
#pragma unroll
                for (int ky = 0; ky < K; ky++)
                    load_row<Sin, ALIGN>(r[ky], base + ky * PSin);

#pragma unroll
                for (int ky = 0; ky < K; ky++) {
                    if (WB) {
                        float wv[CPG * K];
#pragma unroll
                        for (int c = 0; c < CPG; c++) {
                            int co = co0 + c;
                            if (co >= Cout) break;
#pragma unroll
                            for (int kz = 0; kz < K; kz++)
                                wv[c * K + kz] =
                                    sw[((((co * Cin + ci) * K + kw) * K + kx) * K + ky) * K + kz];
                        }
#pragma unroll
                        for (int c = 0; c < CPG; c++) {
                            int co = co0 + c;
                            if (co >= Cout) break;
#pragma unroll
                            for (int kz = 0; kz < K; kz++) {
                                float w = wv[c * K + kz];
#pragma unroll
                                for (int z = 0; z < Sout; z++)
                                    acc[c * Sout + z] += r[ky][z + kz] * w;
                            }
                        }
                    } else {
#pragma unroll
                        for (int c = 0; c < CPG; c++) {
                            int co = co0 + c;
                            if (co >= Cout) break;
#pragma unroll
                            for (int kz = 0; kz < K; kz++) {
                                float w = sw[((((co * Cin + ci) * K + kw) * K + kx) * K + ky) * K + kz];
#pragma unroll
                                for (int z = 0; z < Sout; z++)
                                    acc[c * Sout + z] += r[ky][z + kz] * w;
                            }
                        }
                    }
                }
            }
        }
    }

#pragma unroll
    for (int c = 0; c < CPG; c++) {
        int co = co0 + c;
        if (co >= Cout) break;
        float* op = out +
            ((((b * Cout + co) * Sout + w0) * Sout + x0) * Sout + y0) * PSout;
#pragma unroll
        for (int z = 0; z < Sout; z++)
            op[z] = fmaxf(acc[c * Sout + z], 0.0f);
    }
}

// ---------------------------------------------------------------------------
// Head: per-sample block. dense 1280->33 (ReLU), dense 33->2, softmax.
// ---------------------------------------------------------------------------
__global__ void __launch_bounds__(64)
head_kernel(const float* __restrict__ h,
            const float* __restrict__ dw1, const float* __restrict__ db1,
            const float* __restrict__ dw2, const float* __restrict__ db2,
            float* __restrict__ out)
{
    int b = blockIdx.x;
    __shared__ float sh[1280];
    __shared__ float s1[33];

    for (int i = threadIdx.x; i < 1280; i += blockDim.x)
        sh[i] = h[b * 1280 + i];
    __syncthreads();

    int j = threadIdx.x;
    if (j < 33) {
        float s = db1[j];
        const float* wr = dw1 + j * 1280;
#pragma unroll 4
        for (int i = 0; i < 1280; i++) s += wr[i] * sh[i];
        s1[j] = fmaxf(s, 0.0f);
    }
    __syncthreads();

    if (threadIdx.x == 0) {
        float l0 = db2[0], l1 = db2[1];
        for (int jj = 0; jj < 33; jj++) {
            l0 += dw2[jj] * s1[jj];
            l1 += dw2[33 + jj] * s1[jj];
        }
        float m  = fmaxf(l0, l1);
        float e0 = expf(l0 - m);
        float e1 = expf(l1 - m);
        float inv = 1.0f / (e0 + e1);
        out[b * 2 + 0] = e0 * inv;
        out[b * 2 + 1] = e1 * inv;
    }
}

static inline int cdiv(int a, int b) { return (a + b - 1) / b; }

extern "C" void kernel_launch(void* const* d_in, const int* in_sizes, int n_in,
                              void* d_out, int out_size)
{
    const float* x   = (const float*)d_in[0];
    const float* w1  = (const float*)d_in[1];
    const float* b1  = (const float*)d_in[2];
    const float* w2  = (const float*)d_in[3];
    const float* b2  = (const float*)d_in[4];
    const float* w3  = (const float*)d_in[5];
    const float* b3  = (const float*)d_in[6];
    const float* w4  = (const float*)d_in[7];
    const float* b4  = (const float*)d_in[8];
    const float* w5  = (const float*)d_in[9];
    const float* b5  = (const float*)d_in[10];
    const float* dw1 = (const float*)d_in[11];
    const float* db1 = (const float*)d_in[12];
    const float* dw2 = (const float*)d_in[13];
    const float* db2 = (const float*)d_in[14];
    float* out = (float*)d_out;

    float *h1, *h2, *h3, *h4, *h5;
    cudaGetSymbolAddress((void**)&h1, g_h1);
    cudaGetSymbolAddress((void**)&h2, g_h2);
    cudaGetSymbolAddress((void**)&h3, g_h3);
    cudaGetSymbolAddress((void**)&h4, g_h4);
    cudaGetSymbolAddress((void**)&h5, g_h5);

    const int T = 128;

    // conv1: 1->3, 18->15, k=4. EXACT round-3 config (float2 in, natural out).
    conv4d_relu_kernel<1, 3, 18, 4, 1, 18, 15, 2, 0>
        <<<cdiv(BATCH * 15 * 15 * 15, T), T>>>(x, w1, b1, h1);
    // conv2: 3->3, 15->12, k=4. EXACT round-3 config (scalar in, natural out).
    conv4d_relu_kernel<3, 3, 15, 4, 1, 15, 12, 1, 0>
        <<<cdiv(BATCH * 12 * 12 * 12, T), T>>>(h1, w2, b2, h2);
    // conv3: 3->4, 12->9, k=4. float4 reads of h2 (natural stride 12 = 48B),
    // writes h3 padded stride 12, batched weights.
    conv4d_relu_kernel<3, 4, 12, 4, 1, 12, 12, 4, 1>
        <<<cdiv(BATCH * 9 * 9 * 9, T), T>>>(h2, w3, b3, h3);
    // conv4: 4->5, 9->6, k=4. float4 reads h3 (stride 12), co split x2,
    // writes h4 padded stride 8. Measured 108us in round 4.
    conv4d_relu_kernel<4, 5, 9, 4, 2, 12, 8, 4, 1>
        <<<cdiv(BATCH * 6 * 6 * 6 * 2, T), T>>>(h3, w4, b4, h4);
    // conv5: 5->5, 6->4, k=3. float4 reads h4 (stride 8), co split x5.
    conv4d_relu_kernel<5, 5, 6, 3, 5, 8, 4, 4, 1>
        <<<cdiv(BATCH * 4 * 4 * 4 * 5, T), T>>>(h4, w5, b5, h5);
    // head
    head_kernel<<<BATCH, 64>>>(h5, dw1, db1, dw2, db2, out);
}

// round 10
// speedup vs baseline: 1.6729x; 1.0309x over previous
#include <cuda_runtime.h>
#include <math.h>

// ---------------------------------------------------------------------------
// Model1_11596411699487: 5x 4D conv (valid, stride 1) + ReLU, flatten,
// dense 1280->33 + ReLU, dense 33->2, softmax.
//
// Round 9: h1 z-stride padded to 16 so conv2 gets float4 row loads
// (the measured conv4-style L1-wavefront win), NO z-split. Vectorized
// stores on all layers (all output row bases 16B-aligned now).
// ---------------------------------------------------------------------------

#define BATCH 256

__device__ float g_h1[BATCH * 3 * 15 * 15 * 15 * 16];  // z-stride padded 15->16
__device__ float g_h2[BATCH * 3 * 12 * 12 * 12 * 12];  // natural stride 12 (16B aligned)
__device__ float g_h3[BATCH * 4 * 9 * 9 * 9 * 12];     // z-stride padded 9->12
__device__ float g_h4[BATCH * 5 * 6 * 6 * 6 * 8];      // z-stride padded 6->8
__device__ float g_h5[BATCH * 5 * 4 * 4 * 4 * 4];      // exact (feeds head)

// Exact-length vectorized row load. ALIGN = compile-time guaranteed alignment
// (in floats) of p.
template <int EXT, int ALIGN>
__device__ __forceinline__ void load_row(float* __restrict__ r,
                                         const float* __restrict__ p)
{
    constexpr int N4 = (ALIGN >= 4) ? EXT / 4 : 0;
    constexpr int R4 = EXT - 4 * N4;
    constexpr int N2 = (ALIGN >= 2) ? R4 / 2 : 0;
    constexpr int N1 = R4 - 2 * N2;
#pragma unroll
    for (int j = 0; j < N4; j++) {
        float4 v = *(const float4*)(p + 4 * j);
        r[4 * j + 0] = v.x; r[4 * j + 1] = v.y;
        r[4 * j + 2] = v.z; r[4 * j + 3] = v.w;
    }
#pragma unroll
    for (int j = 0; j < N2; j++) {
        float2 v = *(const float2*)(p + 4 * N4 + 2 * j);
        r[4 * N4 + 2 * j + 0] = v.x;
        r[4 * N4 + 2 * j + 1] = v.y;
    }
#pragma unroll
    for (int j = 0; j < N1; j++)
        r[4 * N4 + 2 * N2 + j] = p[4 * N4 + 2 * N2 + j];
}

// Exact-length vectorized row store (ReLU applied by caller into r).
template <int EXT, int ALIGN>
__device__ __forceinline__ void store_row(float* __restrict__ p,
                                          const float* __restrict__ r)
{
    constexpr int N4 = (ALIGN >= 4) ? EXT / 4 : 0;
    constexpr int R4 = EXT - 4 * N4;
    constexpr int N2 = (ALIGN >= 2) ? R4 / 2 : 0;
    constexpr int N1 = R4 - 2 * N2;
#pragma unroll
    for (int j = 0; j < N4; j++) {
        float4 v;
        v.x = r[4 * j + 0]; v.y = r[4 * j + 1];
        v.z = r[4 * j + 2]; v.w = r[4 * j + 3];
        *(float4*)(p + 4 * j) = v;
    }
#pragma unroll
    for (int j = 0; j < N2; j++) {
        float2 v;
        v.x = r[4 * N4 + 2 * j + 0];
        v.y = r[4 * N4 + 2 * j + 1];
        *(float2*)(p + 4 * N4 + 2 * j) = v;
    }
#pragma unroll
    for (int j = 0; j < N1; j++)
        p[4 * N4 + 2 * N2 + j] = r[4 * N4 + 2 * N2 + j];
}

// ---------------------------------------------------------------------------
// Direct 4D conv + ReLU.
// Thread owns (cog, b, w0, x0, y0): all Sout z outputs for CPG channels.
// Per (ci,kw,kx): batch-load all K ky-rows, then dense FFMA block.
//   PSin/PSout: z-strides of input/output tensors (padded where noted).
//   ALIGN/OALIGN: guaranteed alignment (floats) of input/output row bases.
//   WB: batch weight LDS into registers per ky.
// ---------------------------------------------------------------------------
template <int Cin, int Cout, int Sin, int K, int COG,
          int PSin, int PSout, int ALIGN, int OALIGN, int WB>
__global__ void __launch_bounds__(128)
conv4d_relu_kernel(const float* __restrict__ in,
                   const float* __restrict__ wt,
                   const float* __restrict__ bias,
                   float* __restrict__ out)
{
    constexpr int Sout = Sin - K + 1;
    constexpr int CPG  = (Cout + COG - 1) / COG;
    constexpr int WSZ  = Cout * Cin * K * K * K * K;
    constexpr int NPOS = Sout * Sout * Sout;

    __shared__ float sw[WSZ];
    __shared__ float sb[Cout];
    for (int i = threadIdx.x; i < WSZ; i += blockDim.x) sw[i] = wt[i];
    if (threadIdx.x < Cout) sb[threadIdx.x] = bias[threadIdx.x];
    __syncthreads();

    int tid = blockIdx.x * blockDim.x + threadIdx.x;
    if (tid >= BATCH * NPOS * COG) return;

    int y0 = tid % Sout;
    int t1 = tid / Sout;
    int x0 = t1 % Sout;
    int t2 = t1 / Sout;
    int w0 = t2 % Sout;
    int t3 = t2 / Sout;
    int b  = t3 % BATCH;
    int g  = t3 / BATCH;
    int co0 = g * CPG;

    float acc[CPG * Sout];
#pragma unroll
    for (int c = 0; c < CPG; c++) {
        float bv = (co0 + c < Cout) ? sb[co0 + c] : 0.0f;
#pragma unroll
        for (int z = 0; z < Sout; z++) acc[c * Sout + z] = bv;
    }

#pragma unroll 1
    for (int ci = 0; ci < Cin; ci++) {
#pragma unroll 1
        for (int kw = 0; kw < K; kw++) {
#pragma unroll 1
            for (int kx = 0; kx < K; kx++) {
                const float* base = in +
                    (size_t)((((b * Cin + ci) * Sin + (w0 + kw)) * Sin + (x0 + kx)) * Sin
                             + y0) * PSin;
                float r[K][Sin];
#pragma unroll
                for (int ky = 0; ky < K; ky++)
                    load_row<Sin, ALIGN>(r[ky], base + ky * PSin);

#pragma unroll
                for (int ky = 0; ky < K; ky++) {
                    if (WB) {
                        float wv[CPG * K];
#pragma unroll
                        for (int c = 0; c < CPG; c++) {
                            int co = co0 + c;
                            if (co >= Cout) break;
#pragma unroll
                            for (int kz = 0; kz < K; kz++)
                                wv[c * K + kz] =
                                    sw[((((co * Cin + ci) * K + kw) * K + kx) * K + ky) * K + kz];
                        }
#pragma unroll
                        for (int c = 0; c < CPG; c++) {
                            int co = co0 + c;
                            if (co >= Cout) break;
#pragma unroll
                            for (int kz = 0; kz < K; kz++) {
                                float w = wv[c * K + kz];
#pragma unroll
                                for (int z = 0; z < Sout; z++)
                                    acc[c * Sout + z] += r[ky][z + kz] * w;
                            }
                        }
                    } else {
#pragma unroll
                        for (int c = 0; c < CPG; c++) {
                            int co = co0 + c;
                            if (co >= Cout) break;
#pragma unroll
                            for (int kz = 0; kz < K; kz++) {
                                float w = sw[((((co * Cin + ci) * K + kw) * K + kx) * K + ky) * K + kz];
#pragma unroll
                                for (int z = 0; z < Sout; z++)
                                    acc[c * Sout + z] += r[ky][z + kz] * w;
                            }
                        }
                    }
                }
            }
        }
    }

#pragma unroll
    for (int c = 0; c < CPG; c++) {
        int co = co0 + c;
        if (co >= Cout) break;
        float* op = out +
            (size_t)((((b * Cout + co) * Sout + w0) * Sout + x0) * Sout + y0) * PSout;
        float rr[Sout];
#pragma unroll
        for (int z = 0; z < Sout; z++) rr[z] = fmaxf(acc[c * Sout + z], 0.0f);
        store_row<Sout, OALIGN>(op, rr);
    }
}

// ---------------------------------------------------------------------------
// Head: per-sample block. dense 1280->33 (ReLU), dense 33->2, softmax.
// ---------------------------------------------------------------------------
__global__ void __launch_bounds__(64)
head_kernel(const float* __restrict__ h,
            const float* __restrict__ dw1, const float* __restrict__ db1,
            const float* __restrict__ dw2, const float* __restrict__ db2,
            float* __restrict__ out)
{
    int b = blockIdx.x;
    __shared__ float sh[1280];
    __shared__ float s1[33];

    for (int i = threadIdx.x; i < 1280; i += blockDim.x)
        sh[i] = h[b * 1280 + i];
    __syncthreads();

    int j = threadIdx.x;
    if (j < 33) {
        float s = db1[j];
        const float* wr = dw1 + j * 1280;
#pragma unroll 4
        for (int i = 0; i < 1280; i++) s += wr[i] * sh[i];
        s1[j] = fmaxf(s, 0.0f);
    }
    __syncthreads();

    if (threadIdx.x == 0) {
        float l0 = db2[0], l1 = db2[1];
        for (int jj = 0; jj < 33; jj++) {
            l0 += dw2[jj] * s1[jj];
            l1 += dw2[33 + jj] * s1[jj];
        }
        float m  = fmaxf(l0, l1);
        float e0 = expf(l0 - m);
        float e1 = expf(l1 - m);
        float inv = 1.0f / (e0 + e1);
        out[b * 2 + 0] = e0 * inv;
        out[b * 2 + 1] = e1 * inv;
    }
}

static inline int cdiv(int a, int b) { return (a + b - 1) / b; }

extern "C" void kernel_launch(void* const* d_in, const int* in_sizes, int n_in,
                              void* d_out, int out_size)
{
    const float* x   = (const float*)d_in[0];
    const float* w1  = (const float*)d_in[1];
    const float* b1  = (const float*)d_in[2];
    const float* w2  = (const float*)d_in[3];
    const float* b2  = (const float*)d_in[4];
    const float* w3  = (const float*)d_in[5];
    const float* b3  = (const float*)d_in[6];
    const float* w4  = (const float*)d_in[7];
    const float* b4  = (const float*)d_in[8];
    const float* w5  = (const float*)d_in[9];
    const float* b5  = (const float*)d_in[10];
    const float* dw1 = (const float*)d_in[11];
    const float* db1 = (const float*)d_in[12];
    const float* dw2 = (const float*)d_in[13];
    const float* db2 = (const float*)d_in[14];
    float* out = (float*)d_out;

    float *h1, *h2, *h3, *h4, *h5;
    cudaGetSymbolAddress((void**)&h1, g_h1);
    cudaGetSymbolAddress((void**)&h2, g_h2);
    cudaGetSymbolAddress((void**)&h3, g_h3);
    cudaGetSymbolAddress((void**)&h4, g_h4);
    cudaGetSymbolAddress((void**)&h5, g_h5);

    const int T = 128;

    // conv1: 1->3, 18->15, k=4. float2 in (x stride 18), out h1 stride 16 (f4 stores).
    conv4d_relu_kernel<1, 3, 18, 4, 1, 18, 16, 2, 4, 0>
        <<<cdiv(BATCH * 15 * 15 * 15, T), T>>>(x, w1, b1, h1);
    // conv2: 3->3, 15->12, k=4. float4 reads of h1 (stride 16), NO z-split,
    // out h2 stride 12 (f4 stores). Only load width changed vs 1531us build.
    conv4d_relu_kernel<3, 3, 15, 4, 1, 16, 12, 4, 4, 0>
        <<<cdiv(BATCH * 12 * 12 * 12, T), T>>>(h1, w2, b2, h2);
    // conv3: 3->4, 12->9, k=4. float4 reads h2 (stride 12), out h3 stride 12.
    conv4d_relu_kernel<3, 4, 12, 4, 1, 12, 12, 4, 4, 1>
        <<<cdiv(BATCH * 9 * 9 * 9, T), T>>>(h2, w3, b3, h3);
    // conv4: 4->5, 9->6, k=4. float4 reads h3 (stride 12), co split x2,
    // out h4 stride 8.
    conv4d_relu_kernel<4, 5, 9, 4, 2, 12, 8, 4, 4, 1>
        <<<cdiv(BATCH * 6 * 6 * 6 * 2, T), T>>>(h3, w4, b4, h4);
    // conv5: 5->5, 6->4, k=3. float4 reads h4 (stride 8), co split x5, out exact
    // (stride 4, base 16B-aligned -> f4 store).
    conv4d_relu_kernel<5, 5, 6, 3, 5, 8, 4, 4, 4, 1>
        <<<cdiv(BATCH * 4 * 4 * 4 * 5, T), T>>>(h4, w5, b5, h5);
    // head
    head_kernel<<<BATCH, 64>>>(h5, dw1, db1, dw2, db2, out);
}